// round 10
// baseline (speedup 1.0000x reference)
#include <cuda_runtime.h>
#include <cstdint>
#include <cstddef>

// Problem dims
#define NH    8
#define NSEQ  4096
#define FIN   512
#define HD    64
#define FOUT  512

#define QT 128          // query rows per CTA (8 warps x 16)
#define KT 64           // keys per iteration
#define NIT (NSEQ / KT)

// Scratch (device globals: allocation-free rule)
__device__ float g_Q[NH * NSEQ * HD];   // tf32, pre-scaled by 1/8
__device__ float g_K[NH * NSEQ * HD];   // tf32
__device__ float g_V[NH * NSEQ * HD];   // tf32
__device__ float g_C[NSEQ * NH * HD];   // [n][h*HD+d], tf32-rounded

__device__ __forceinline__ float to_tf32(float x) {
    float r; asm("cvt.rna.tf32.f32 %0, %1;" : "=f"(r) : "f"(x)); return r;
}

// m16n8k8 tf32 MMA
__device__ __forceinline__ void mma8(float* c, const uint32_t* a, uint32_t b0, uint32_t b1) {
    asm volatile(
        "mma.sync.aligned.m16n8k8.row.col.f32.tf32.tf32.f32 "
        "{%0,%1,%2,%3}, {%4,%5,%6,%7}, {%8,%9}, {%0,%1,%2,%3};"
        : "+f"(c[0]), "+f"(c[1]), "+f"(c[2]), "+f"(c[3])
        : "r"(a[0]), "r"(a[1]), "r"(a[2]), "r"(a[3]), "r"(b0), "r"(b1));
}

// ---------------------------------------------------------------------------
// Kernel 1: fused QKV projection via mma.sync tf32 (unchanged, measured ~92us)
// ---------------------------------------------------------------------------
__global__ __launch_bounds__(256, 2) void qkv_kernel(
    const float* __restrict__ X,
    const float* __restrict__ Wq,
    const float* __restrict__ Wk,
    const float* __restrict__ Wv)
{
    __shared__ float Xs[128][36];
    __shared__ float Ws[192][36];

    const int h  = blockIdx.y;
    const int m0 = blockIdx.x * 128;
    const int tid  = threadIdx.x;
    const int wid  = tid >> 5;
    const int lane = tid & 31;
    const int g = lane >> 2;
    const int t = lane & 3;
    const int wrow = wid * 16;

    const float* Xh = X + (size_t)h * NSEQ * FIN;

    float acc[24][4];
    #pragma unroll
    for (int nb = 0; nb < 24; nb++)
        #pragma unroll
        for (int i = 0; i < 4; i++) acc[nb][i] = 0.f;

    for (int f0 = 0; f0 < FIN; f0 += 32) {
        #pragma unroll
        for (int u = 0; u < 4; u++) {
            int idx = tid + u * 256;
            int r = idx >> 3, c4 = (idx & 7) << 2;
            float4 v = *(const float4*)(Xh + (size_t)(m0 + r) * FIN + f0 + c4);
            Xs[r][c4 + 0] = to_tf32(v.x); Xs[r][c4 + 1] = to_tf32(v.y);
            Xs[r][c4 + 2] = to_tf32(v.z); Xs[r][c4 + 3] = to_tf32(v.w);
        }
        #pragma unroll
        for (int u = 0; u < 6; u++) {
            int idx = tid + u * 256;
            int r = idx >> 3, c4 = (idx & 7) << 2;
            const float* Wsel = (r < 64) ? Wq : (r < 128) ? Wk : Wv;
            int d = r & 63;
            float4 v = *(const float4*)(Wsel + ((size_t)h * HD + d) * FIN + f0 + c4);
            Ws[r][c4 + 0] = to_tf32(v.x); Ws[r][c4 + 1] = to_tf32(v.y);
            Ws[r][c4 + 2] = to_tf32(v.z); Ws[r][c4 + 3] = to_tf32(v.w);
        }
        __syncthreads();

        uint32_t a[4][4];
        #pragma unroll
        for (int ks = 0; ks < 4; ks++) {
            const float* Xr = &Xs[wrow + g][ks * 8 + t];
            a[ks][0] = __float_as_uint(Xr[0]);
            a[ks][1] = __float_as_uint(Xr[8 * 36]);
            a[ks][2] = __float_as_uint(Xr[4]);
            a[ks][3] = __float_as_uint(Xr[8 * 36 + 4]);
        }
        #pragma unroll
        for (int nb = 0; nb < 24; nb++) {
            #pragma unroll
            for (int ks = 0; ks < 4; ks++) {
                const float* Wp = &Ws[nb * 8 + g][ks * 8 + t];
                mma8(acc[nb], a[ks], __float_as_uint(Wp[0]), __float_as_uint(Wp[4]));
            }
        }
        __syncthreads();
    }

    #pragma unroll
    for (int nb = 0; nb < 24; nb++) {
        const int mat = nb >> 3;
        const int d0  = (nb & 7) * 8;
        float* Out = (mat == 0) ? g_Q : (mat == 1) ? g_K : g_V;
        const float sc = (mat == 0) ? 0.125f : 1.0f;
        size_t r0 = ((size_t)h * NSEQ + m0 + wrow + g) * HD + d0 + 2 * t;
        float2 v0 = make_float2(to_tf32(acc[nb][0] * sc), to_tf32(acc[nb][1] * sc));
        float2 v1 = make_float2(to_tf32(acc[nb][2] * sc), to_tf32(acc[nb][3] * sc));
        *(float2*)(Out + r0) = v0;
        *(float2*)(Out + r0 + (size_t)8 * HD) = v1;
    }
}

// ---------------------------------------------------------------------------
// Kernel 2: flash attention via mma.sync tf32 (R6 shape: 8 warps x 16 rows),
// with permuted-K and transposed+permuted-V SMEM layouts so that every
// B-fragment (b0,b1) pair is a single LDS.64 instead of two LDS.32.
//
// Column permutation within each 8-col group: i<4 -> 2i ; i>=4 -> 2(i-4)+1.
// Then cols (t, t+4) land at positions (2t, 2t+1): contiguous float2.
// K stored [key][perm(dim)]; V stored transposed [dim][perm(key)].
// ---------------------------------------------------------------------------
#define KV_STRIDE 68
#define SM_V  (64 * KV_STRIDE)
#define SM_P  (2 * 64 * KV_STRIDE)
#define ATTN_SMEM_FLOATS (SM_P + 128 * KV_STRIDE)
#define ATTN_SMEM_BYTES  (ATTN_SMEM_FLOATS * 4)

__global__ __launch_bounds__(256, 2) void attn_kernel(const int* __restrict__ mask)
{
    extern __shared__ float smf[];
    float* Ks = smf;                 // [64 keys][perm dim], stride 68
    float* Vs = smf + SM_V;          // [64 dims][perm key], stride 68
    float* Ps = smf + SM_P;          // P (and initial Q staging), unpermuted

    const int tid  = threadIdx.x;
    const int wid  = tid >> 5;
    const int lane = tid & 31;
    const int g = lane >> 2;
    const int t = lane & 3;

    const int h  = blockIdx.y;
    const int q0 = blockIdx.x * QT;
    const int wrow = wid * 16;

    // ---- Stage Q tile (128x64) into smem (unpermuted), grab fragments ----
    {
        const float* Qg = g_Q + ((size_t)h * NSEQ + q0) * HD;
        for (int idx = tid; idx < 128 * 16; idx += 256) {
            int r = idx >> 4, c4 = (idx & 15) << 2;
            float4 v = *(const float4*)(Qg + (size_t)r * HD + c4);
            *(float4*)(Ps + r * KV_STRIDE + c4) = v;
        }
    }
    __syncthreads();

    uint32_t qa[8][4];
    #pragma unroll
    for (int ks = 0; ks < 8; ks++) {
        const float* Qr = Ps + (wrow + g) * KV_STRIDE + ks * 8 + t;
        qa[ks][0] = __float_as_uint(Qr[0]);
        qa[ks][1] = __float_as_uint(Qr[8 * KV_STRIDE]);
        qa[ks][2] = __float_as_uint(Qr[4]);
        qa[ks][3] = __float_as_uint(Qr[8 * KV_STRIDE + 4]);
    }

    float oacc[8][4];
    #pragma unroll
    for (int nb = 0; nb < 8; nb++)
        #pragma unroll
        for (int i = 0; i < 4; i++) oacc[nb][i] = 0.f;

    float m_lo = -3.0e38f, m_hi = -3.0e38f;
    float l_lo = 0.f, l_hi = 0.f;

    const int* mrow_lo = mask + ((size_t)h * NSEQ + q0 + wrow + g) * NSEQ;
    const int* mrow_hi = mrow_lo + (size_t)8 * NSEQ;

    for (int it = 0; it < NIT; it++) {
        const int k0 = it * KT;
        __syncthreads();

        // ---- cooperative load K (perm cols) and V (transposed, perm keys) ----
        {
            const float* Kg = g_K + ((size_t)h * NSEQ + k0) * HD;
            const float* Vg = g_V + ((size_t)h * NSEQ + k0) * HD;
            #pragma unroll
            for (int u = 0; u < 4; u++) {
                int idx = tid + u * 256;
                int r = idx >> 4, c4 = (idx & 15) << 2;

                // K[r][c4..c4+3] -> Ks[r][perm positions]
                float4 kv = *(const float4*)(Kg + (size_t)r * HD + c4);
                float* kd = Ks + r * KV_STRIDE + (c4 & ~7) + ((c4 & 4) ? 1 : 0);
                kd[0] = kv.x; kd[2] = kv.y; kd[4] = kv.z; kd[6] = kv.w;

                // V[r][c4..c4+3] -> Vs[c4+j][perm(r)]
                float4 vv = *(const float4*)(Vg + (size_t)r * HD + c4);
                int kp = (r & ~7) + ((r & 4) ? ((r & 3) * 2 + 1) : ((r & 3) * 2));
                float* vd = Vs + c4 * KV_STRIDE + kp;
                vd[0]             = vv.x;
                vd[KV_STRIDE]     = vv.y;
                vd[2 * KV_STRIDE] = vv.z;
                vd[3 * KV_STRIDE] = vv.w;
            }
        }
        __syncthreads();

        // ---- S = Q @ K^T : B pair = one LDS.64 ----
        float sacc[8][4];
        #pragma unroll
        for (int nb = 0; nb < 8; nb++)
            #pragma unroll
            for (int i = 0; i < 4; i++) sacc[nb][i] = 0.f;

        #pragma unroll
        for (int ks = 0; ks < 8; ks++) {
            #pragma unroll
            for (int nb = 0; nb < 8; nb++) {
                float2 kb = *(const float2*)(Ks + (nb * 8 + g) * KV_STRIDE + ks * 8 + 2 * t);
                mma8(sacc[nb], qa[ks], __float_as_uint(kb.x), __float_as_uint(kb.y));
            }
        }

        // ---- mask + online softmax ----
        float mx_lo = -3.0e38f, mx_hi = -3.0e38f;
        #pragma unroll
        for (int nb = 0; nb < 8; nb++) {
            int2 ml = *(const int2*)(mrow_lo + k0 + nb * 8 + 2 * t);
            int2 mh = *(const int2*)(mrow_hi + k0 + nb * 8 + 2 * t);
            sacc[nb][0] = ml.x ? sacc[nb][0] : -1e30f;
            sacc[nb][1] = ml.y ? sacc[nb][1] : -1e30f;
            sacc[nb][2] = mh.x ? sacc[nb][2] : -1e30f;
            sacc[nb][3] = mh.y ? sacc[nb][3] : -1e30f;
            mx_lo = fmaxf(mx_lo, fmaxf(sacc[nb][0], sacc[nb][1]));
            mx_hi = fmaxf(mx_hi, fmaxf(sacc[nb][2], sacc[nb][3]));
        }
        mx_lo = fmaxf(mx_lo, __shfl_xor_sync(0xffffffffu, mx_lo, 1));
        mx_lo = fmaxf(mx_lo, __shfl_xor_sync(0xffffffffu, mx_lo, 2));
        mx_hi = fmaxf(mx_hi, __shfl_xor_sync(0xffffffffu, mx_hi, 1));
        mx_hi = fmaxf(mx_hi, __shfl_xor_sync(0xffffffffu, mx_hi, 2));

        float mn_lo = fmaxf(m_lo, mx_lo);
        float mn_hi = fmaxf(m_hi, mx_hi);
        float corr_lo = __expf(m_lo - mn_lo);
        float corr_hi = __expf(m_hi - mn_hi);
        m_lo = mn_lo; m_hi = mn_hi;

        float s_lo = 0.f, s_hi = 0.f;
        #pragma unroll
        for (int nb = 0; nb < 8; nb++) {
            sacc[nb][0] = __expf(sacc[nb][0] - mn_lo);
            sacc[nb][1] = __expf(sacc[nb][1] - mn_lo);
            sacc[nb][2] = __expf(sacc[nb][2] - mn_hi);
            sacc[nb][3] = __expf(sacc[nb][3] - mn_hi);
            s_lo += sacc[nb][0] + sacc[nb][1];
            s_hi += sacc[nb][2] + sacc[nb][3];
        }
        s_lo += __shfl_xor_sync(0xffffffffu, s_lo, 1);
        s_lo += __shfl_xor_sync(0xffffffffu, s_lo, 2);
        s_hi += __shfl_xor_sync(0xffffffffu, s_hi, 1);
        s_hi += __shfl_xor_sync(0xffffffffu, s_hi, 2);
        l_lo = l_lo * corr_lo + s_lo;
        l_hi = l_hi * corr_hi + s_hi;

        #pragma unroll
        for (int nb = 0; nb < 8; nb++) {
            oacc[nb][0] *= corr_lo; oacc[nb][1] *= corr_lo;
            oacc[nb][2] *= corr_hi; oacc[nb][3] *= corr_hi;
        }

        // ---- stage P (tf32) into warp-private smem rows (unpermuted) ----
        #pragma unroll
        for (int nb = 0; nb < 8; nb++) {
            float2 plo = make_float2(to_tf32(sacc[nb][0]), to_tf32(sacc[nb][1]));
            float2 phi = make_float2(to_tf32(sacc[nb][2]), to_tf32(sacc[nb][3]));
            *(float2*)(Ps + (wrow + g) * KV_STRIDE + nb * 8 + 2 * t)     = plo;
            *(float2*)(Ps + (wrow + g + 8) * KV_STRIDE + nb * 8 + 2 * t) = phi;
        }
        __syncwarp();

        // ---- O += P @ V : B pair = one LDS.64 from transposed V ----
        #pragma unroll
        for (int ks = 0; ks < 8; ks++) {
            uint32_t pa[4];
            const float* Pp = Ps + (wrow + g) * KV_STRIDE + ks * 8 + t;
            pa[0] = __float_as_uint(Pp[0]);
            pa[1] = __float_as_uint(Pp[8 * KV_STRIDE]);
            pa[2] = __float_as_uint(Pp[4]);
            pa[3] = __float_as_uint(Pp[8 * KV_STRIDE + 4]);
            #pragma unroll
            for (int nb = 0; nb < 8; nb++) {
                float2 vb = *(const float2*)(Vs + (nb * 8 + g) * KV_STRIDE + ks * 8 + 2 * t);
                mma8(oacc[nb], pa, __float_as_uint(vb.x), __float_as_uint(vb.y));
            }
        }
    }

    // ---- normalize, tf32-round, write Hcat ----
    float inv_lo = 1.f / l_lo;
    float inv_hi = 1.f / l_hi;
    float* Crow_lo = g_C + (size_t)(q0 + wrow + g) * (NH * HD) + h * HD;
    float* Crow_hi = Crow_lo + (size_t)8 * (NH * HD);
    #pragma unroll
    for (int nb = 0; nb < 8; nb++) {
        float2 lo = make_float2(to_tf32(oacc[nb][0] * inv_lo), to_tf32(oacc[nb][1] * inv_lo));
        float2 hi = make_float2(to_tf32(oacc[nb][2] * inv_hi), to_tf32(oacc[nb][3] * inv_hi));
        *(float2*)(Crow_lo + nb * 8 + 2 * t) = lo;
        *(float2*)(Crow_hi + nb * 8 + 2 * t) = hi;
    }
}

// ---------------------------------------------------------------------------
// Kernel 3: output projection via mma.sync tf32 (unchanged)
// ---------------------------------------------------------------------------
__global__ __launch_bounds__(256, 2) void proj_kernel(
    const float* __restrict__ Wo, float* __restrict__ out)
{
    __shared__ float Cs[128][36];
    __shared__ float Ws[128][36];

    const int m0 = blockIdx.x * 128;
    const int n0 = blockIdx.y * 128;
    const int tid  = threadIdx.x;
    const int lane = tid & 31;
    const int g = lane >> 2;
    const int t = lane & 3;
    const int wrow = (tid >> 5) * 16;

    float acc[16][4];
    #pragma unroll
    for (int nb = 0; nb < 16; nb++)
        #pragma unroll
        for (int i = 0; i < 4; i++) acc[nb][i] = 0.f;

    for (int f0 = 0; f0 < FIN; f0 += 32) {
        #pragma unroll
        for (int u = 0; u < 4; u++) {
            int idx = tid + u * 256;
            int r = idx >> 3, c4 = (idx & 7) << 2;
            float4 cv = *(const float4*)(g_C + (size_t)(m0 + r) * (NH * HD) + f0 + c4);
            Cs[r][c4 + 0] = cv.x; Cs[r][c4 + 1] = cv.y;
            Cs[r][c4 + 2] = cv.z; Cs[r][c4 + 3] = cv.w;
            float4 wv = *(const float4*)(Wo + (size_t)(n0 + r) * (NH * HD) + f0 + c4);
            Ws[r][c4 + 0] = to_tf32(wv.x); Ws[r][c4 + 1] = to_tf32(wv.y);
            Ws[r][c4 + 2] = to_tf32(wv.z); Ws[r][c4 + 3] = to_tf32(wv.w);
        }
        __syncthreads();

        uint32_t a[4][4];
        #pragma unroll
        for (int ks = 0; ks < 4; ks++) {
            const float* Cr = &Cs[wrow + g][ks * 8 + t];
            a[ks][0] = __float_as_uint(Cr[0]);
            a[ks][1] = __float_as_uint(Cr[8 * 36]);
            a[ks][2] = __float_as_uint(Cr[4]);
            a[ks][3] = __float_as_uint(Cr[8 * 36 + 4]);
        }
        #pragma unroll
        for (int nb = 0; nb < 16; nb++) {
            #pragma unroll
            for (int ks = 0; ks < 4; ks++) {
                const float* Wp = &Ws[nb * 8 + g][ks * 8 + t];
                mma8(acc[nb], a[ks], __float_as_uint(Wp[0]), __float_as_uint(Wp[4]));
            }
        }
        __syncthreads();
    }

    #pragma unroll
    for (int nb = 0; nb < 16; nb++) {
        size_t r0 = (size_t)(m0 + wrow + g) * FOUT + n0 + nb * 8 + 2 * t;
        *(float2*)(out + r0) = make_float2(acc[nb][0], acc[nb][1]);
        *(float2*)(out + r0 + (size_t)8 * FOUT) = make_float2(acc[nb][2], acc[nb][3]);
    }
}

// ---------------------------------------------------------------------------
extern "C" void kernel_launch(void* const* d_in, const int* in_sizes, int n_in,
                              void* d_out, int out_size)
{
    const float* X    = (const float*)d_in[0];
    const int*   mask = (const int*)  d_in[1];
    const float* Wq   = (const float*)d_in[2];
    const float* Wk   = (const float*)d_in[3];
    const float* Wv   = (const float*)d_in[4];
    const float* Wo   = (const float*)d_in[5];
    float*       out  = (float*)d_out;

    cudaFuncSetAttribute(attn_kernel,
                         cudaFuncAttributeMaxDynamicSharedMemorySize, ATTN_SMEM_BYTES);

    qkv_kernel<<<dim3(NSEQ / 128, NH), 256>>>(X, Wq, Wk, Wv);
    attn_kernel<<<dim3(NSEQ / QT, NH), 256, ATTN_SMEM_BYTES>>>(mask);
    proj_kernel<<<dim3(NSEQ / 128, FOUT / 128), 256>>>(Wo, out);
}

// round 11
// speedup vs baseline: 1.7929x; 1.7929x over previous
#include <cuda_runtime.h>
#include <cstdint>
#include <cstddef>

// Problem dims
#define NH    8
#define NSEQ  4096
#define FIN   512
#define HD    64
#define FOUT  512

#define QT 128          // query rows per CTA (8 warps x 16)
#define KT 64           // keys per iteration
#define NIT (NSEQ / KT)

// Scratch (device globals: allocation-free rule)
__device__ float g_Q[NH * NSEQ * HD];   // tf32, pre-scaled by 1/8
__device__ float g_K[NH * NSEQ * HD];   // tf32
__device__ float g_V[NH * NSEQ * HD];   // tf32
__device__ float g_C[NSEQ * NH * HD];   // [n][h*HD+d], tf32-rounded
// Bit-packed mask: word (s*4+c) of row r holds, at bit l, mask[r][s*128 + l*4 + c]
__device__ uint32_t g_Mb[NH * NSEQ * 128];   // 16 MB

__device__ __forceinline__ float to_tf32(float x) {
    float r; asm("cvt.rna.tf32.f32 %0, %1;" : "=f"(r) : "f"(x)); return r;
}

// m16n8k8 tf32 MMA
__device__ __forceinline__ void mma8(float* c, const uint32_t* a, uint32_t b0, uint32_t b1) {
    asm volatile(
        "mma.sync.aligned.m16n8k8.row.col.f32.tf32.tf32.f32 "
        "{%0,%1,%2,%3}, {%4,%5,%6,%7}, {%8,%9}, {%0,%1,%2,%3};"
        : "+f"(c[0]), "+f"(c[1]), "+f"(c[2]), "+f"(c[3])
        : "r"(a[0]), "r"(a[1]), "r"(a[2]), "r"(a[3]), "r"(b0), "r"(b1));
}

// ---------------------------------------------------------------------------
// Kernel 1: fused QKV projection via mma.sync tf32 (unchanged, measured ~92us)
// ---------------------------------------------------------------------------
__global__ __launch_bounds__(256, 2) void qkv_kernel(
    const float* __restrict__ X,
    const float* __restrict__ Wq,
    const float* __restrict__ Wk,
    const float* __restrict__ Wv)
{
    __shared__ float Xs[128][36];
    __shared__ float Ws[192][36];

    const int h  = blockIdx.y;
    const int m0 = blockIdx.x * 128;
    const int tid  = threadIdx.x;
    const int wid  = tid >> 5;
    const int lane = tid & 31;
    const int g = lane >> 2;
    const int t = lane & 3;
    const int wrow = wid * 16;

    const float* Xh = X + (size_t)h * NSEQ * FIN;

    float acc[24][4];
    #pragma unroll
    for (int nb = 0; nb < 24; nb++)
        #pragma unroll
        for (int i = 0; i < 4; i++) acc[nb][i] = 0.f;

    for (int f0 = 0; f0 < FIN; f0 += 32) {
        #pragma unroll
        for (int u = 0; u < 4; u++) {
            int idx = tid + u * 256;
            int r = idx >> 3, c4 = (idx & 7) << 2;
            float4 v = *(const float4*)(Xh + (size_t)(m0 + r) * FIN + f0 + c4);
            Xs[r][c4 + 0] = to_tf32(v.x); Xs[r][c4 + 1] = to_tf32(v.y);
            Xs[r][c4 + 2] = to_tf32(v.z); Xs[r][c4 + 3] = to_tf32(v.w);
        }
        #pragma unroll
        for (int u = 0; u < 6; u++) {
            int idx = tid + u * 256;
            int r = idx >> 3, c4 = (idx & 7) << 2;
            const float* Wsel = (r < 64) ? Wq : (r < 128) ? Wk : Wv;
            int d = r & 63;
            float4 v = *(const float4*)(Wsel + ((size_t)h * HD + d) * FIN + f0 + c4);
            Ws[r][c4 + 0] = to_tf32(v.x); Ws[r][c4 + 1] = to_tf32(v.y);
            Ws[r][c4 + 2] = to_tf32(v.z); Ws[r][c4 + 3] = to_tf32(v.w);
        }
        __syncthreads();

        uint32_t a[4][4];
        #pragma unroll
        for (int ks = 0; ks < 4; ks++) {
            const float* Xr = &Xs[wrow + g][ks * 8 + t];
            a[ks][0] = __float_as_uint(Xr[0]);
            a[ks][1] = __float_as_uint(Xr[8 * 36]);
            a[ks][2] = __float_as_uint(Xr[4]);
            a[ks][3] = __float_as_uint(Xr[8 * 36 + 4]);
        }
        #pragma unroll
        for (int nb = 0; nb < 24; nb++) {
            #pragma unroll
            for (int ks = 0; ks < 4; ks++) {
                const float* Wp = &Ws[nb * 8 + g][ks * 8 + t];
                mma8(acc[nb], a[ks], __float_as_uint(Wp[0]), __float_as_uint(Wp[4]));
            }
        }
        __syncthreads();
    }

    #pragma unroll
    for (int nb = 0; nb < 24; nb++) {
        const int mat = nb >> 3;
        const int d0  = (nb & 7) * 8;
        float* Out = (mat == 0) ? g_Q : (mat == 1) ? g_K : g_V;
        const float sc = (mat == 0) ? 0.125f : 1.0f;
        size_t r0 = ((size_t)h * NSEQ + m0 + wrow + g) * HD + d0 + 2 * t;
        float2 v0 = make_float2(to_tf32(acc[nb][0] * sc), to_tf32(acc[nb][1] * sc));
        float2 v1 = make_float2(to_tf32(acc[nb][2] * sc), to_tf32(acc[nb][3] * sc));
        *(float2*)(Out + r0) = v0;
        *(float2*)(Out + r0 + (size_t)8 * HD) = v1;
    }
}

// ---------------------------------------------------------------------------
// Kernel 1b: mask bit-pack. mask[row][k] (int32) -> g_Mb[row][128] (bits).
// Word (s*4+c), bit l  <->  key s*128 + l*4 + c.
// grid = 2048, block = 256 (8 warps); warp packs 2 rows.
// ---------------------------------------------------------------------------
__global__ __launch_bounds__(256) void pack_kernel(const int* __restrict__ mask)
{
    const int wid  = threadIdx.x >> 5;
    const int lane = threadIdx.x & 31;
    const int gw = blockIdx.x * 8 + wid;       // 0..16383

    #pragma unroll
    for (int rr = 0; rr < 2; rr++) {
        const int row = gw * 2 + rr;           // 0..32767 = h*NSEQ + n
        const int* src = mask + (size_t)row * NSEQ;
        uint32_t* dst = g_Mb + (size_t)row * 128;
        #pragma unroll 4
        for (int s = 0; s < 32; s++) {
            int4 v = *(const int4*)(src + s * 128 + lane * 4);
            uint32_t b0 = __ballot_sync(0xffffffffu, v.x != 0);
            uint32_t b1 = __ballot_sync(0xffffffffu, v.y != 0);
            uint32_t b2 = __ballot_sync(0xffffffffu, v.z != 0);
            uint32_t b3 = __ballot_sync(0xffffffffu, v.w != 0);
            if (lane == 0)
                *(uint4*)(dst + s * 4) = make_uint4(b0, b1, b2, b3);
        }
    }
}

// ---------------------------------------------------------------------------
// Kernel 2: flash attention via mma.sync tf32 (R6 shape, best measured),
// mask read from bit-packed g_Mb: 2 x LDG.128 per thread per iteration.
// grid = (NSEQ/128, NH), block = 256 (8 warps x 16 query rows).
// ---------------------------------------------------------------------------
#define KV_STRIDE 68
#define SM_V  (64 * KV_STRIDE)
#define SM_P  (2 * 64 * KV_STRIDE)
#define ATTN_SMEM_FLOATS (SM_P + 128 * KV_STRIDE)
#define ATTN_SMEM_BYTES  (ATTN_SMEM_FLOATS * 4)

__global__ __launch_bounds__(256, 2) void attn_kernel(int dummy)
{
    extern __shared__ float smf[];
    float* Ks = smf;
    float* Vs = smf + SM_V;
    float* Ps = smf + SM_P;

    const int tid  = threadIdx.x;
    const int wid  = tid >> 5;
    const int lane = tid & 31;
    const int g = lane >> 2;
    const int t = lane & 3;

    const int h  = blockIdx.y;
    const int q0 = blockIdx.x * QT;
    const int wrow = wid * 16;

    // ---- Stage Q tile (128x64) into smem, grab fragments ----
    {
        const float* Qg = g_Q + ((size_t)h * NSEQ + q0) * HD;
        for (int idx = tid; idx < 128 * 16; idx += 256) {
            int r = idx >> 4, c4 = (idx & 15) << 2;
            float4 v = *(const float4*)(Qg + (size_t)r * HD + c4);
            *(float4*)(smf + r * KV_STRIDE + c4) = v;
        }
    }
    __syncthreads();

    uint32_t qa[8][4];
    #pragma unroll
    for (int ks = 0; ks < 8; ks++) {
        const float* Qr = smf + (wrow + g) * KV_STRIDE + ks * 8 + t;
        qa[ks][0] = __float_as_uint(Qr[0]);
        qa[ks][1] = __float_as_uint(Qr[8 * KV_STRIDE]);
        qa[ks][2] = __float_as_uint(Qr[4]);
        qa[ks][3] = __float_as_uint(Qr[8 * KV_STRIDE + 4]);
    }

    float oacc[8][4];
    #pragma unroll
    for (int nb = 0; nb < 8; nb++)
        #pragma unroll
        for (int i = 0; i < 4; i++) oacc[nb][i] = 0.f;

    float m_lo = -3.0e38f, m_hi = -3.0e38f;
    float l_lo = 0.f, l_hi = 0.f;

    // packed mask rows for this thread's two fragment rows
    const uint32_t* mbp_lo = g_Mb + (size_t)((h * NSEQ) + q0 + wrow + g) * 128;
    const uint32_t* mbp_hi = mbp_lo + (size_t)8 * 128;

    for (int it = 0; it < NIT; it++) {
        const int k0 = it * KT;
        __syncthreads();

        // ---- cooperative load K,V tiles (64x64 each) ----
        {
            const float* Kg = g_K + ((size_t)h * NSEQ + k0) * HD;
            const float* Vg = g_V + ((size_t)h * NSEQ + k0) * HD;
            #pragma unroll
            for (int u = 0; u < 4; u++) {
                int idx = tid + u * 256;
                int r = idx >> 4, c4 = (idx & 15) << 2;
                float4 kv = *(const float4*)(Kg + (size_t)r * HD + c4);
                *(float4*)(Ks + r * KV_STRIDE + c4) = kv;
                float4 vv = *(const float4*)(Vg + (size_t)r * HD + c4);
                *(float4*)(Vs + r * KV_STRIDE + c4) = vv;
            }
        }

        // packed mask words for this 64-key tile (2 x LDG.128, L2-resident)
        const uint4 wl = *(const uint4*)(mbp_lo + ((it >> 1) << 2));
        const uint4 wh = *(const uint4*)(mbp_hi + ((it >> 1) << 2));
        __syncthreads();

        // ---- S = Q @ K^T ----
        float sacc[8][4];
        #pragma unroll
        for (int nb = 0; nb < 8; nb++)
            #pragma unroll
            for (int i = 0; i < 4; i++) sacc[nb][i] = 0.f;

        #pragma unroll
        for (int ks = 0; ks < 8; ks++) {
            #pragma unroll
            for (int nb = 0; nb < 8; nb++) {
                const float* Kp = Ks + (nb * 8 + g) * KV_STRIDE + ks * 8 + t;
                mma8(sacc[nb], qa[ks], __float_as_uint(Kp[0]), __float_as_uint(Kp[4]));
            }
        }

        // ---- mask (bit tests) + online softmax ----
        // key K = it*64 + nb*8 + 2t (+1): c = (2t)&3 (+1), l = 16*(it&1) + 2*nb + t/2
        const uint32_t we_lo = (t & 1) ? wl.z : wl.x;
        const uint32_t wo_lo = (t & 1) ? wl.w : wl.y;
        const uint32_t we_hi = (t & 1) ? wh.z : wh.x;
        const uint32_t wo_hi = (t & 1) ? wh.w : wh.y;
        const int lbase = ((it & 1) << 4) + (t >> 1);

        float mx_lo = -3.0e38f, mx_hi = -3.0e38f;
        #pragma unroll
        for (int nb = 0; nb < 8; nb++) {
            const int l = lbase + 2 * nb;
            sacc[nb][0] = ((we_lo >> l) & 1u) ? sacc[nb][0] : -1e30f;
            sacc[nb][1] = ((wo_lo >> l) & 1u) ? sacc[nb][1] : -1e30f;
            sacc[nb][2] = ((we_hi >> l) & 1u) ? sacc[nb][2] : -1e30f;
            sacc[nb][3] = ((wo_hi >> l) & 1u) ? sacc[nb][3] : -1e30f;
            mx_lo = fmaxf(mx_lo, fmaxf(sacc[nb][0], sacc[nb][1]));
            mx_hi = fmaxf(mx_hi, fmaxf(sacc[nb][2], sacc[nb][3]));
        }
        mx_lo = fmaxf(mx_lo, __shfl_xor_sync(0xffffffffu, mx_lo, 1));
        mx_lo = fmaxf(mx_lo, __shfl_xor_sync(0xffffffffu, mx_lo, 2));
        mx_hi = fmaxf(mx_hi, __shfl_xor_sync(0xffffffffu, mx_hi, 1));
        mx_hi = fmaxf(mx_hi, __shfl_xor_sync(0xffffffffu, mx_hi, 2));

        float mn_lo = fmaxf(m_lo, mx_lo);
        float mn_hi = fmaxf(m_hi, mx_hi);
        float corr_lo = __expf(m_lo - mn_lo);
        float corr_hi = __expf(m_hi - mn_hi);
        m_lo = mn_lo; m_hi = mn_hi;

        float s_lo = 0.f, s_hi = 0.f;
        #pragma unroll
        for (int nb = 0; nb < 8; nb++) {
            sacc[nb][0] = __expf(sacc[nb][0] - mn_lo);
            sacc[nb][1] = __expf(sacc[nb][1] - mn_lo);
            sacc[nb][2] = __expf(sacc[nb][2] - mn_hi);
            sacc[nb][3] = __expf(sacc[nb][3] - mn_hi);
            s_lo += sacc[nb][0] + sacc[nb][1];
            s_hi += sacc[nb][2] + sacc[nb][3];
        }
        s_lo += __shfl_xor_sync(0xffffffffu, s_lo, 1);
        s_lo += __shfl_xor_sync(0xffffffffu, s_lo, 2);
        s_hi += __shfl_xor_sync(0xffffffffu, s_hi, 1);
        s_hi += __shfl_xor_sync(0xffffffffu, s_hi, 2);
        l_lo = l_lo * corr_lo + s_lo;
        l_hi = l_hi * corr_hi + s_hi;

        #pragma unroll
        for (int nb = 0; nb < 8; nb++) {
            oacc[nb][0] *= corr_lo; oacc[nb][1] *= corr_lo;
            oacc[nb][2] *= corr_hi; oacc[nb][3] *= corr_hi;
        }

        // ---- stage P (tf32) into warp-private smem rows ----
        #pragma unroll
        for (int nb = 0; nb < 8; nb++) {
            float2 plo = make_float2(to_tf32(sacc[nb][0]), to_tf32(sacc[nb][1]));
            float2 phi = make_float2(to_tf32(sacc[nb][2]), to_tf32(sacc[nb][3]));
            *(float2*)(Ps + (wrow + g) * KV_STRIDE + nb * 8 + 2 * t)     = plo;
            *(float2*)(Ps + (wrow + g + 8) * KV_STRIDE + nb * 8 + 2 * t) = phi;
        }
        __syncwarp();

        // ---- O += P @ V ----
        #pragma unroll
        for (int ks = 0; ks < 8; ks++) {
            uint32_t pa[4];
            const float* Pp = Ps + (wrow + g) * KV_STRIDE + ks * 8 + t;
            pa[0] = __float_as_uint(Pp[0]);
            pa[1] = __float_as_uint(Pp[8 * KV_STRIDE]);
            pa[2] = __float_as_uint(Pp[4]);
            pa[3] = __float_as_uint(Pp[8 * KV_STRIDE + 4]);
            #pragma unroll
            for (int nb = 0; nb < 8; nb++) {
                const float* Vp = Vs + (ks * 8 + t) * KV_STRIDE + nb * 8 + g;
                mma8(oacc[nb], pa, __float_as_uint(Vp[0]),
                     __float_as_uint(Vp[4 * KV_STRIDE]));
            }
        }
    }

    // ---- normalize, tf32-round, write Hcat ----
    float inv_lo = 1.f / l_lo;
    float inv_hi = 1.f / l_hi;
    float* Crow_lo = g_C + (size_t)(q0 + wrow + g) * (NH * HD) + h * HD;
    float* Crow_hi = Crow_lo + (size_t)8 * (NH * HD);
    #pragma unroll
    for (int nb = 0; nb < 8; nb++) {
        float2 lo = make_float2(to_tf32(oacc[nb][0] * inv_lo), to_tf32(oacc[nb][1] * inv_lo));
        float2 hi = make_float2(to_tf32(oacc[nb][2] * inv_hi), to_tf32(oacc[nb][3] * inv_hi));
        *(float2*)(Crow_lo + nb * 8 + 2 * t) = lo;
        *(float2*)(Crow_hi + nb * 8 + 2 * t) = hi;
    }
}

// ---------------------------------------------------------------------------
// Kernel 3: output projection via mma.sync tf32 (unchanged)
// ---------------------------------------------------------------------------
__global__ __launch_bounds__(256, 2) void proj_kernel(
    const float* __restrict__ Wo, float* __restrict__ out)
{
    __shared__ float Cs[128][36];
    __shared__ float Ws[128][36];

    const int m0 = blockIdx.x * 128;
    const int n0 = blockIdx.y * 128;
    const int tid  = threadIdx.x;
    const int lane = tid & 31;
    const int g = lane >> 2;
    const int t = lane & 3;
    const int wrow = (tid >> 5) * 16;

    float acc[16][4];
    #pragma unroll
    for (int nb = 0; nb < 16; nb++)
        #pragma unroll
        for (int i = 0; i < 4; i++) acc[nb][i] = 0.f;

    for (int f0 = 0; f0 < FIN; f0 += 32) {
        #pragma unroll
        for (int u = 0; u < 4; u++) {
            int idx = tid + u * 256;
            int r = idx >> 3, c4 = (idx & 7) << 2;
            float4 cv = *(const float4*)(g_C + (size_t)(m0 + r) * (NH * HD) + f0 + c4);
            Cs[r][c4 + 0] = cv.x; Cs[r][c4 + 1] = cv.y;
            Cs[r][c4 + 2] = cv.z; Cs[r][c4 + 3] = cv.w;
            float4 wv = *(const float4*)(Wo + (size_t)(n0 + r) * (NH * HD) + f0 + c4);
            Ws[r][c4 + 0] = to_tf32(wv.x); Ws[r][c4 + 1] = to_tf32(wv.y);
            Ws[r][c4 + 2] = to_tf32(wv.z); Ws[r][c4 + 3] = to_tf32(wv.w);
        }
        __syncthreads();

        uint32_t a[4][4];
        #pragma unroll
        for (int ks = 0; ks < 4; ks++) {
            const float* Cr = &Cs[wrow + g][ks * 8 + t];
            a[ks][0] = __float_as_uint(Cr[0]);
            a[ks][1] = __float_as_uint(Cr[8 * 36]);
            a[ks][2] = __float_as_uint(Cr[4]);
            a[ks][3] = __float_as_uint(Cr[8 * 36 + 4]);
        }
        #pragma unroll
        for (int nb = 0; nb < 16; nb++) {
            #pragma unroll
            for (int ks = 0; ks < 4; ks++) {
                const float* Wp = &Ws[nb * 8 + g][ks * 8 + t];
                mma8(acc[nb], a[ks], __float_as_uint(Wp[0]), __float_as_uint(Wp[4]));
            }
        }
        __syncthreads();
    }

    #pragma unroll
    for (int nb = 0; nb < 16; nb++) {
        size_t r0 = (size_t)(m0 + wrow + g) * FOUT + n0 + nb * 8 + 2 * t;
        *(float2*)(out + r0) = make_float2(acc[nb][0], acc[nb][1]);
        *(float2*)(out + r0 + (size_t)8 * FOUT) = make_float2(acc[nb][2], acc[nb][3]);
    }
}

// ---------------------------------------------------------------------------
extern "C" void kernel_launch(void* const* d_in, const int* in_sizes, int n_in,
                              void* d_out, int out_size)
{
    const float* X    = (const float*)d_in[0];
    const int*   mask = (const int*)  d_in[1];
    const float* Wq   = (const float*)d_in[2];
    const float* Wk   = (const float*)d_in[3];
    const float* Wv   = (const float*)d_in[4];
    const float* Wo   = (const float*)d_in[5];
    float*       out  = (float*)d_out;

    cudaFuncSetAttribute(attn_kernel,
                         cudaFuncAttributeMaxDynamicSharedMemorySize, ATTN_SMEM_BYTES);

    // 4 launches/replay => attn lands at launch index 6 (ncu -s 5 -c 1 captures it)
    qkv_kernel<<<dim3(NSEQ / 128, NH), 256>>>(X, Wq, Wk, Wv);
    pack_kernel<<<2048, 256>>>(mask);
    attn_kernel<<<dim3(NSEQ / QT, NH), 256, ATTN_SMEM_BYTES>>>(0);
    proj_kernel<<<dim3(NSEQ / 128, FOUT / 128), 256>>>(Wo, out);
}

// round 12
// speedup vs baseline: 1.9294x; 1.0761x over previous
#include <cuda_runtime.h>
#include <cstdint>
#include <cstddef>

// Problem dims
#define NH    8
#define NSEQ  4096
#define FIN   512
#define HD    64
#define FOUT  512

#define QT 128          // query rows per CTA (8 warps x 16)
#define KT 64           // keys per iteration
#define NIT (NSEQ / KT)

// Scratch (device globals: allocation-free rule)
__device__ float g_Q[NH * NSEQ * HD];   // tf32, pre-scaled by 1/8
__device__ float g_K[NH * NSEQ * HD];   // tf32
__device__ float g_V[NH * NSEQ * HD];   // tf32
__device__ float g_C[NSEQ * NH * HD];   // [n][h*HD+d], tf32-rounded

__device__ __forceinline__ float to_tf32(float x) {
    float r; asm("cvt.rna.tf32.f32 %0, %1;" : "=f"(r) : "f"(x)); return r;
}

// m16n8k8 tf32 MMA
__device__ __forceinline__ void mma8(float* c, const uint32_t* a, uint32_t b0, uint32_t b1) {
    asm volatile(
        "mma.sync.aligned.m16n8k8.row.col.f32.tf32.tf32.f32 "
        "{%0,%1,%2,%3}, {%4,%5,%6,%7}, {%8,%9}, {%0,%1,%2,%3};"
        : "+f"(c[0]), "+f"(c[1]), "+f"(c[2]), "+f"(c[3])
        : "r"(a[0]), "r"(a[1]), "r"(a[2]), "r"(a[3]), "r"(b0), "r"(b1));
}

// ---------------------------------------------------------------------------
// Kernel 1: QKV projection via mma.sync tf32, one matrix per CTA (z axis).
// grid = (NSEQ/128, NH, 3), block = 256 (8 warps x 16 rows).
// acc = 32 regs/thread -> 3 CTAs/SM (24 warps) for latency hiding.
// Numerically identical to the fused version (same f0/ks order, tf32 rounding).
// ---------------------------------------------------------------------------
__global__ __launch_bounds__(256, 3) void qkv_kernel(
    const float* __restrict__ X,
    const float* __restrict__ Wq,
    const float* __restrict__ Wk,
    const float* __restrict__ Wv)
{
    __shared__ float Xs[128][36];
    __shared__ float Ws[64][36];

    const int h  = blockIdx.y;
    const int m0 = blockIdx.x * 128;
    const int z  = blockIdx.z;
    const float* W = (z == 0) ? Wq : (z == 1) ? Wk : Wv;
    float* Out     = (z == 0) ? g_Q : (z == 1) ? g_K : g_V;
    const float sc = (z == 0) ? 0.125f : 1.0f;   // fold 1/sqrt(64) into Q

    const int tid  = threadIdx.x;
    const int wid  = tid >> 5;
    const int lane = tid & 31;
    const int g = lane >> 2;
    const int t = lane & 3;
    const int wrow = wid * 16;

    const float* Xh = X + (size_t)h * NSEQ * FIN;
    const float* Wh = W + (size_t)h * HD * FIN;

    float acc[8][4];
    #pragma unroll
    for (int nb = 0; nb < 8; nb++)
        #pragma unroll
        for (int i = 0; i < 4; i++) acc[nb][i] = 0.f;

    for (int f0 = 0; f0 < FIN; f0 += 32) {
        // X tile 128x32 (1024 float4 -> 4/thread), tf32-rounded
        #pragma unroll
        for (int u = 0; u < 4; u++) {
            int idx = tid + u * 256;
            int r = idx >> 3, c4 = (idx & 7) << 2;
            float4 v = *(const float4*)(Xh + (size_t)(m0 + r) * FIN + f0 + c4);
            Xs[r][c4 + 0] = to_tf32(v.x); Xs[r][c4 + 1] = to_tf32(v.y);
            Xs[r][c4 + 2] = to_tf32(v.z); Xs[r][c4 + 3] = to_tf32(v.w);
        }
        // W tile 64x32 (512 float4 -> 2/thread), tf32-rounded
        #pragma unroll
        for (int u = 0; u < 2; u++) {
            int idx = tid + u * 256;
            int r = idx >> 3, c4 = (idx & 7) << 2;
            float4 v = *(const float4*)(Wh + (size_t)r * FIN + f0 + c4);
            Ws[r][c4 + 0] = to_tf32(v.x); Ws[r][c4 + 1] = to_tf32(v.y);
            Ws[r][c4 + 2] = to_tf32(v.z); Ws[r][c4 + 3] = to_tf32(v.w);
        }
        __syncthreads();

        uint32_t a[4][4];
        #pragma unroll
        for (int ks = 0; ks < 4; ks++) {
            const float* Xr = &Xs[wrow + g][ks * 8 + t];
            a[ks][0] = __float_as_uint(Xr[0]);
            a[ks][1] = __float_as_uint(Xr[8 * 36]);
            a[ks][2] = __float_as_uint(Xr[4]);
            a[ks][3] = __float_as_uint(Xr[8 * 36 + 4]);
        }
        #pragma unroll
        for (int nb = 0; nb < 8; nb++) {
            #pragma unroll
            for (int ks = 0; ks < 4; ks++) {
                const float* Wp = &Ws[nb * 8 + g][ks * 8 + t];
                mma8(acc[nb], a[ks], __float_as_uint(Wp[0]), __float_as_uint(Wp[4]));
            }
        }
        __syncthreads();
    }

    #pragma unroll
    for (int nb = 0; nb < 8; nb++) {
        size_t r0 = ((size_t)h * NSEQ + m0 + wrow + g) * HD + nb * 8 + 2 * t;
        float2 v0 = make_float2(to_tf32(acc[nb][0] * sc), to_tf32(acc[nb][1] * sc));
        float2 v1 = make_float2(to_tf32(acc[nb][2] * sc), to_tf32(acc[nb][3] * sc));
        *(float2*)(Out + r0) = v0;
        *(float2*)(Out + r0 + (size_t)8 * HD) = v1;
    }
}

// ---------------------------------------------------------------------------
// Kernel 2: flash attention via mma.sync tf32 (R6 version, measured 412us —
// the best of five structural variants; kept byte-identical).
// grid = (NSEQ/128, NH), block = 256 (8 warps x 16 query rows).
// ---------------------------------------------------------------------------
#define KV_STRIDE 68
#define SM_V  (64 * KV_STRIDE)
#define SM_P  (2 * 64 * KV_STRIDE)
#define ATTN_SMEM_FLOATS (SM_P + 128 * KV_STRIDE)
#define ATTN_SMEM_BYTES  (ATTN_SMEM_FLOATS * 4)

__global__ __launch_bounds__(256, 2) void attn_kernel(const int* __restrict__ mask)
{
    extern __shared__ float smf[];
    float* Ks = smf;
    float* Vs = smf + SM_V;
    float* Ps = smf + SM_P;

    const int tid  = threadIdx.x;
    const int wid  = tid >> 5;
    const int lane = tid & 31;
    const int g = lane >> 2;
    const int t = lane & 3;

    const int h  = blockIdx.y;
    const int q0 = blockIdx.x * QT;
    const int wrow = wid * 16;

    // ---- Stage Q tile (128x64) into smem, grab fragments ----
    {
        const float* Qg = g_Q + ((size_t)h * NSEQ + q0) * HD;
        for (int idx = tid; idx < 128 * 16; idx += 256) {
            int r = idx >> 4, c4 = (idx & 15) << 2;
            float4 v = *(const float4*)(Qg + (size_t)r * HD + c4);
            *(float4*)(smf + r * KV_STRIDE + c4) = v;
        }
    }
    __syncthreads();

    uint32_t qa[8][4];
    #pragma unroll
    for (int ks = 0; ks < 8; ks++) {
        const float* Qr = smf + (wrow + g) * KV_STRIDE + ks * 8 + t;
        qa[ks][0] = __float_as_uint(Qr[0]);
        qa[ks][1] = __float_as_uint(Qr[8 * KV_STRIDE]);
        qa[ks][2] = __float_as_uint(Qr[4]);
        qa[ks][3] = __float_as_uint(Qr[8 * KV_STRIDE + 4]);
    }

    float oacc[8][4];
    #pragma unroll
    for (int nb = 0; nb < 8; nb++)
        #pragma unroll
        for (int i = 0; i < 4; i++) oacc[nb][i] = 0.f;

    float m_lo = -3.0e38f, m_hi = -3.0e38f;
    float l_lo = 0.f, l_hi = 0.f;

    const int* mrow_lo = mask + ((size_t)h * NSEQ + q0 + wrow + g) * NSEQ;
    const int* mrow_hi = mrow_lo + (size_t)8 * NSEQ;

    for (int it = 0; it < NIT; it++) {
        const int k0 = it * KT;
        __syncthreads();

        // ---- cooperative load K,V tiles (64x64 each) ----
        {
            const float* Kg = g_K + ((size_t)h * NSEQ + k0) * HD;
            const float* Vg = g_V + ((size_t)h * NSEQ + k0) * HD;
            #pragma unroll
            for (int u = 0; u < 4; u++) {
                int idx = tid + u * 256;
                int r = idx >> 4, c4 = (idx & 15) << 2;
                float4 kv = *(const float4*)(Kg + (size_t)r * HD + c4);
                *(float4*)(Ks + r * KV_STRIDE + c4) = kv;
                float4 vv = *(const float4*)(Vg + (size_t)r * HD + c4);
                *(float4*)(Vs + r * KV_STRIDE + c4) = vv;
            }
        }
        __syncthreads();

        // ---- S = Q @ K^T ----
        float sacc[8][4];
        #pragma unroll
        for (int nb = 0; nb < 8; nb++)
            #pragma unroll
            for (int i = 0; i < 4; i++) sacc[nb][i] = 0.f;

        #pragma unroll
        for (int ks = 0; ks < 8; ks++) {
            #pragma unroll
            for (int nb = 0; nb < 8; nb++) {
                const float* Kp = Ks + (nb * 8 + g) * KV_STRIDE + ks * 8 + t;
                mma8(sacc[nb], qa[ks], __float_as_uint(Kp[0]), __float_as_uint(Kp[4]));
            }
        }

        // ---- mask + online softmax ----
        float mx_lo = -3.0e38f, mx_hi = -3.0e38f;
        #pragma unroll
        for (int nb = 0; nb < 8; nb++) {
            int2 ml = *(const int2*)(mrow_lo + k0 + nb * 8 + 2 * t);
            int2 mh = *(const int2*)(mrow_hi + k0 + nb * 8 + 2 * t);
            sacc[nb][0] = ml.x ? sacc[nb][0] : -1e30f;
            sacc[nb][1] = ml.y ? sacc[nb][1] : -1e30f;
            sacc[nb][2] = mh.x ? sacc[nb][2] : -1e30f;
            sacc[nb][3] = mh.y ? sacc[nb][3] : -1e30f;
            mx_lo = fmaxf(mx_lo, fmaxf(sacc[nb][0], sacc[nb][1]));
            mx_hi = fmaxf(mx_hi, fmaxf(sacc[nb][2], sacc[nb][3]));
        }
        mx_lo = fmaxf(mx_lo, __shfl_xor_sync(0xffffffffu, mx_lo, 1));
        mx_lo = fmaxf(mx_lo, __shfl_xor_sync(0xffffffffu, mx_lo, 2));
        mx_hi = fmaxf(mx_hi, __shfl_xor_sync(0xffffffffu, mx_hi, 1));
        mx_hi = fmaxf(mx_hi, __shfl_xor_sync(0xffffffffu, mx_hi, 2));

        float mn_lo = fmaxf(m_lo, mx_lo);
        float mn_hi = fmaxf(m_hi, mx_hi);
        float corr_lo = __expf(m_lo - mn_lo);
        float corr_hi = __expf(m_hi - mn_hi);
        m_lo = mn_lo; m_hi = mn_hi;

        float s_lo = 0.f, s_hi = 0.f;
        #pragma unroll
        for (int nb = 0; nb < 8; nb++) {
            sacc[nb][0] = __expf(sacc[nb][0] - mn_lo);
            sacc[nb][1] = __expf(sacc[nb][1] - mn_lo);
            sacc[nb][2] = __expf(sacc[nb][2] - mn_hi);
            sacc[nb][3] = __expf(sacc[nb][3] - mn_hi);
            s_lo += sacc[nb][0] + sacc[nb][1];
            s_hi += sacc[nb][2] + sacc[nb][3];
        }
        s_lo += __shfl_xor_sync(0xffffffffu, s_lo, 1);
        s_lo += __shfl_xor_sync(0xffffffffu, s_lo, 2);
        s_hi += __shfl_xor_sync(0xffffffffu, s_hi, 1);
        s_hi += __shfl_xor_sync(0xffffffffu, s_hi, 2);
        l_lo = l_lo * corr_lo + s_lo;
        l_hi = l_hi * corr_hi + s_hi;

        #pragma unroll
        for (int nb = 0; nb < 8; nb++) {
            oacc[nb][0] *= corr_lo; oacc[nb][1] *= corr_lo;
            oacc[nb][2] *= corr_hi; oacc[nb][3] *= corr_hi;
        }

        // ---- stage P (tf32) into warp-private smem rows ----
        #pragma unroll
        for (int nb = 0; nb < 8; nb++) {
            float2 plo = make_float2(to_tf32(sacc[nb][0]), to_tf32(sacc[nb][1]));
            float2 phi = make_float2(to_tf32(sacc[nb][2]), to_tf32(sacc[nb][3]));
            *(float2*)(Ps + (wrow + g) * KV_STRIDE + nb * 8 + 2 * t)     = plo;
            *(float2*)(Ps + (wrow + g + 8) * KV_STRIDE + nb * 8 + 2 * t) = phi;
        }
        __syncwarp();

        // ---- O += P @ V ----
        #pragma unroll
        for (int ks = 0; ks < 8; ks++) {
            uint32_t pa[4];
            const float* Pp = Ps + (wrow + g) * KV_STRIDE + ks * 8 + t;
            pa[0] = __float_as_uint(Pp[0]);
            pa[1] = __float_as_uint(Pp[8 * KV_STRIDE]);
            pa[2] = __float_as_uint(Pp[4]);
            pa[3] = __float_as_uint(Pp[8 * KV_STRIDE + 4]);
            #pragma unroll
            for (int nb = 0; nb < 8; nb++) {
                const float* Vp = Vs + (ks * 8 + t) * KV_STRIDE + nb * 8 + g;
                mma8(oacc[nb], pa, __float_as_uint(Vp[0]),
                     __float_as_uint(Vp[4 * KV_STRIDE]));
            }
        }
    }

    // ---- normalize, tf32-round, write Hcat ----
    float inv_lo = 1.f / l_lo;
    float inv_hi = 1.f / l_hi;
    float* Crow_lo = g_C + (size_t)(q0 + wrow + g) * (NH * HD) + h * HD;
    float* Crow_hi = Crow_lo + (size_t)8 * (NH * HD);
    #pragma unroll
    for (int nb = 0; nb < 8; nb++) {
        float2 lo = make_float2(to_tf32(oacc[nb][0] * inv_lo), to_tf32(oacc[nb][1] * inv_lo));
        float2 hi = make_float2(to_tf32(oacc[nb][2] * inv_hi), to_tf32(oacc[nb][3] * inv_hi));
        *(float2*)(Crow_lo + nb * 8 + 2 * t) = lo;
        *(float2*)(Crow_hi + nb * 8 + 2 * t) = hi;
    }
}

// ---------------------------------------------------------------------------
// Kernel 3: output projection via mma.sync tf32 (unchanged, measured ~31us)
// ---------------------------------------------------------------------------
__global__ __launch_bounds__(256, 2) void proj_kernel(
    const float* __restrict__ Wo, float* __restrict__ out)
{
    __shared__ float Cs[128][36];
    __shared__ float Ws[128][36];

    const int m0 = blockIdx.x * 128;
    const int n0 = blockIdx.y * 128;
    const int tid  = threadIdx.x;
    const int lane = tid & 31;
    const int g = lane >> 2;
    const int t = lane & 3;
    const int wrow = (tid >> 5) * 16;

    float acc[16][4];
    #pragma unroll
    for (int nb = 0; nb < 16; nb++)
        #pragma unroll
        for (int i = 0; i < 4; i++) acc[nb][i] = 0.f;

    for (int f0 = 0; f0 < FIN; f0 += 32) {
        #pragma unroll
        for (int u = 0; u < 4; u++) {
            int idx = tid + u * 256;
            int r = idx >> 3, c4 = (idx & 7) << 2;
            float4 cv = *(const float4*)(g_C + (size_t)(m0 + r) * (NH * HD) + f0 + c4);
            Cs[r][c4 + 0] = cv.x; Cs[r][c4 + 1] = cv.y;
            Cs[r][c4 + 2] = cv.z; Cs[r][c4 + 3] = cv.w;
            float4 wv = *(const float4*)(Wo + (size_t)(n0 + r) * (NH * HD) + f0 + c4);
            Ws[r][c4 + 0] = to_tf32(wv.x); Ws[r][c4 + 1] = to_tf32(wv.y);
            Ws[r][c4 + 2] = to_tf32(wv.z); Ws[r][c4 + 3] = to_tf32(wv.w);
        }
        __syncthreads();

        uint32_t a[4][4];
        #pragma unroll
        for (int ks = 0; ks < 4; ks++) {
            const float* Cr = &Cs[wrow + g][ks * 8 + t];
            a[ks][0] = __float_as_uint(Cr[0]);
            a[ks][1] = __float_as_uint(Cr[8 * 36]);
            a[ks][2] = __float_as_uint(Cr[4]);
            a[ks][3] = __float_as_uint(Cr[8 * 36 + 4]);
        }
        #pragma unroll
        for (int nb = 0; nb < 16; nb++) {
            #pragma unroll
            for (int ks = 0; ks < 4; ks++) {
                const float* Wp = &Ws[nb * 8 + g][ks * 8 + t];
                mma8(acc[nb], a[ks], __float_as_uint(Wp[0]), __float_as_uint(Wp[4]));
            }
        }
        __syncthreads();
    }

    #pragma unroll
    for (int nb = 0; nb < 16; nb++) {
        size_t r0 = (size_t)(m0 + wrow + g) * FOUT + n0 + nb * 8 + 2 * t;
        *(float2*)(out + r0) = make_float2(acc[nb][0], acc[nb][1]);
        *(float2*)(out + r0 + (size_t)8 * FOUT) = make_float2(acc[nb][2], acc[nb][3]);
    }
}

// ---------------------------------------------------------------------------
extern "C" void kernel_launch(void* const* d_in, const int* in_sizes, int n_in,
                              void* d_out, int out_size)
{
    const float* X    = (const float*)d_in[0];
    const int*   mask = (const int*)  d_in[1];
    const float* Wq   = (const float*)d_in[2];
    const float* Wk   = (const float*)d_in[3];
    const float* Wv   = (const float*)d_in[4];
    const float* Wo   = (const float*)d_in[5];
    float*       out  = (float*)d_out;

    cudaFuncSetAttribute(attn_kernel,
                         cudaFuncAttributeMaxDynamicSharedMemorySize, ATTN_SMEM_BYTES);

    qkv_kernel<<<dim3(NSEQ / 128, NH, 3), 256>>>(X, Wq, Wk, Wv);
    attn_kernel<<<dim3(NSEQ / QT, NH), 256, ATTN_SMEM_BYTES>>>(mask);
    proj_kernel<<<dim3(NSEQ / 128, FOUT / 128), 256>>>(Wo, out);
}